// round 2
// baseline (speedup 1.0000x reference)
#include <cuda_runtime.h>

#define B 8
#define M 2048
#define N 2048
#define IN 256
#define TM 32
#define TN 1024

// ---- scratch (allocation-free: __device__ globals) ----
__device__ float g_v0[IN];          // W0^T @ Wc[:128]
__device__ float g_v1[IN];          // W1^T @ Wc[128:]
__device__ float g_consts[2];       // dot(b0,wc0) ; dot(b1,wc1)+bc
__device__ float g_s0[B * M];       // s0 + const0
__device__ float g_ls0[B * M];      // logsig(z0)
__device__ float g_lsn0[B * M];     // logsig(-z0)
__device__ float g_s1b[B * N];      // s1 + const1 (bc folded in)
__device__ float g_ls1[B * N];      // logsig(z1)
__device__ float g_lsn1[B * N];     // logsig(-z1)

__device__ __forceinline__ float lsig(float x) {
    // log_sigmoid(x) = min(x,0) - log1p(exp(-|x|)); fast-math variant.
    return fminf(x, 0.0f) - __logf(1.0f + __expf(-fabsf(x)));
}

// ---- kernel 0: fold projection weights through Wc; compute bias constants ----
__global__ void prep_kernel(const float* __restrict__ W0, const float* __restrict__ b0,
                            const float* __restrict__ W1, const float* __restrict__ b1,
                            const float* __restrict__ Wc, const float* __restrict__ bc) {
    int i = threadIdx.x;  // 0..255
    float a0 = 0.f, a1 = 0.f;
    #pragma unroll 4
    for (int d = 0; d < 128; d++) {
        a0 += W0[d * IN + i] * Wc[d];
        a1 += W1[d * IN + i] * Wc[128 + d];
    }
    g_v0[i] = a0;
    g_v1[i] = a1;

    int w = i >> 5, l = i & 31;
    if (w == 0) {
        float c = 0.f;
        for (int d = l; d < 128; d += 32) c += b0[d] * Wc[d];
        #pragma unroll
        for (int o = 16; o; o >>= 1) c += __shfl_down_sync(0xffffffffu, c, o);
        if (l == 0) g_consts[0] = c;
    } else if (w == 1) {
        float c = 0.f;
        for (int d = l; d < 128; d += 32) c += b1[d] * Wc[128 + d];
        #pragma unroll
        for (int o = 16; o; o >>= 1) c += __shfl_down_sync(0xffffffffu, c, o);
        if (l == 0) g_consts[1] = c + bc[0];
    }
}

// ---- kernel 1: per-row dot products; one warp per row ----
__global__ void rows_kernel(const float* __restrict__ d0, const float* __restrict__ d1,
                            const float* __restrict__ Wm, const float* __restrict__ bm) {
    int which = blockIdx.y;                 // 0 -> desc0, 1 -> desc1
    const float* desc = which ? d1 : d0;
    const float* v    = which ? g_v1 : g_v0;
    int warp = threadIdx.x >> 5, lane = threadIdx.x & 31;
    int row = blockIdx.x * 8 + warp;        // B*M rows total

    const float4* dp = (const float4*)(desc + (size_t)row * IN);
    const float4* vp = (const float4*)v;
    const float4* wp = (const float4*)Wm;

    float as = 0.f, az = 0.f;
    #pragma unroll
    for (int j = 0; j < 2; j++) {
        int k = lane + j * 32;              // 64 float4 per row
        float4 dv = dp[k];
        float4 vv = vp[k];
        float4 wv = wp[k];
        as += dv.x * vv.x + dv.y * vv.y + dv.z * vv.z + dv.w * vv.w;
        az += dv.x * wv.x + dv.y * wv.y + dv.z * wv.z + dv.w * wv.w;
    }
    #pragma unroll
    for (int o = 16; o; o >>= 1) {
        as += __shfl_down_sync(0xffffffffu, as, o);
        az += __shfl_down_sync(0xffffffffu, az, o);
    }
    if (lane == 0) {
        float z = az + bm[0];
        if (which == 0) {
            g_s0[row]  = as + g_consts[0];
            g_ls0[row] = lsig(z);
            g_lsn0[row] = lsig(-z);
        } else {
            g_s1b[row] = as + g_consts[1];
            g_ls1[row] = lsig(z);
            g_lsn1[row] = lsig(-z);
        }
    }
}

// ---- kernel 2: fill inner region of probs + corres ----
// Block tile: TM=32 rows x TN=1024 cols, 256 threads.
// Thread t owns columns n0 + t + j*256 (j=0..3): every STG is fully coalesced
// scalar stores (probs row stride 2049 breaks float4 alignment).
__global__ void __launch_bounds__(256) main_kernel(float* __restrict__ probs,
                                                   float* __restrict__ corres,
                                                   int has_corres) {
    int b  = blockIdx.z;
    int m0 = blockIdx.y * TM;
    int n0 = blockIdx.x * TN;
    int tx = threadIdx.x;

    __shared__ float sh_s0[TM];
    __shared__ float sh_ls0[TM];
    if (tx < TM) {
        int r = b * M + m0 + tx;
        sh_s0[tx]  = g_s0[r];
        sh_ls0[tx] = g_ls0[r];
    }

    float s1v[4], ls1v[4];
    #pragma unroll
    for (int j = 0; j < 4; j++) {
        int n = n0 + tx + j * 256;
        s1v[j]  = g_s1b[b * N + n];
        ls1v[j] = g_ls1[b * N + n];
    }
    __syncthreads();

    size_t pbase = (size_t)b * (M + 1) * (N + 1);
    size_t cbase = (size_t)b * M * N;
    const bool wc = (has_corres != 0);

    #pragma unroll 4
    for (int r = 0; r < TM; r++) {
        int m = m0 + r;
        float s0 = sh_s0[r];
        float l0 = sh_ls0[r];
        float* prow = probs + pbase + (size_t)m * (N + 1) + n0 + tx;
        float* crow = corres + cbase + (size_t)m * N + n0 + tx;
        #pragma unroll
        for (int j = 0; j < 4; j++) {
            float c = s0 + s1v[j];
            float inner = lsig(c) + l0 + ls1v[j];
            prow[j * 256] = inner;
            if (wc) crow[j * 256] = c;
        }
    }
}

// ---- kernel 3: edges of probs (last column, last row, corner) ----
__global__ void edge_kernel(float* __restrict__ probs) {
    int idx = blockIdx.x * blockDim.x + threadIdx.x;  // 0..B*M-1
    int b = idx / M, k = idx % M;
    size_t pbase = (size_t)b * (M + 1) * (N + 1);
    probs[pbase + (size_t)k * (N + 1) + N] = g_lsn0[b * M + k];  // probs[:, :m, n]
    probs[pbase + (size_t)M * (N + 1) + k] = g_lsn1[b * N + k];  // probs[:, m, :n]
    if (k == 0) probs[pbase + (size_t)M * (N + 1) + N] = 0.0f;   // corner
}

extern "C" void kernel_launch(void* const* d_in, const int* in_sizes, int n_in,
                              void* d_out, int out_size) {
    const float* desc0 = (const float*)d_in[0];
    const float* desc1 = (const float*)d_in[1];
    const float* W0    = (const float*)d_in[2];
    const float* b0    = (const float*)d_in[3];
    const float* W1    = (const float*)d_in[4];
    const float* b1    = (const float*)d_in[5];
    const float* Wm    = (const float*)d_in[6];
    const float* bm    = (const float*)d_in[7];
    const float* Wc    = (const float*)d_in[8];
    const float* bc    = (const float*)d_in[9];

    float* out = (float*)d_out;
    long long probs_elems  = (long long)B * (M + 1) * (N + 1);
    long long corres_elems = (long long)B * M * N;
    int has_corres = ((long long)out_size >= probs_elems + corres_elems) ? 1 : 0;
    float* probs  = out;
    float* corres = out + probs_elems;

    prep_kernel<<<1, 256>>>(W0, b0, W1, b1, Wc, bc);
    rows_kernel<<<dim3(B * M / 8, 2), 256>>>(desc0, desc1, Wm, bm);
    main_kernel<<<dim3(N / TN, M / TM, B), 256>>>(probs, corres, has_corres);
    edge_kernel<<<(B * M) / 256, 256>>>(probs);
}